// round 13
// baseline (speedup 1.0000x reference)
#include <cuda_runtime.h>
#include <cuda_fp16.h>
#include <cstdint>

#define DIM 64
#define N_AGENTS_MAX 50000
#define XS 68

__device__ float g_sum[N_AGENTS_MAX * DIM];
__device__ float g_cnt[N_AGENTS_MAX];

// ---------------- phi smem layout (bytes) ----------------
#define OFF_WHI   0          // 8192   W1 fp16 (init only; B frags hoisted to regs)
#define OFF_XHI   8192       // 16384  X fp16 [128][64] swizzled
#define OFF_H     24576      // 17408  h fp16 [128] rows, 136B stride
#define OFF_BIAS  41984      // 256
#define OFF_SEG   42240      // 544
#define PHI_SMEM  42784

// ---------------- rho smem layout (bytes) ----------------
#define R_W2      0
#define R_RW1     8192
#define R_XHI     16384
#define R_XLO     32768
#define R_B2      49152
#define R_RB1     49408
#define R_RW2     49664
#define R_CNT     50176
#define RHO_SMEM  50688

__device__ __forceinline__ uint32_t smem_u32(const void* p) {
    uint32_t a;
    asm("{ .reg .u64 t; cvta.to.shared.u64 t, %1; cvt.u32.u64 %0, t; }" : "=r"(a) : "l"(p));
    return a;
}
__device__ __forceinline__ void ldsm_x4(uint32_t* r, uint32_t addr) {
    asm volatile("ldmatrix.sync.aligned.m8n8.x4.shared.b16 {%0,%1,%2,%3}, [%4];"
        : "=r"(r[0]), "=r"(r[1]), "=r"(r[2]), "=r"(r[3]) : "r"(addr));
}
__device__ __forceinline__ void ldsm_x4_trans(uint32_t* r, uint32_t addr) {
    asm volatile("ldmatrix.sync.aligned.m8n8.x4.trans.shared.b16 {%0,%1,%2,%3}, [%4];"
        : "=r"(r[0]), "=r"(r[1]), "=r"(r[2]), "=r"(r[3]) : "r"(addr));
}
__device__ __forceinline__ void mma_f16(float* d, const uint32_t* a, uint32_t b0, uint32_t b1) {
    asm volatile("mma.sync.aligned.m16n8k16.row.col.f32.f16.f16.f32 "
        "{%0,%1,%2,%3}, {%4,%5,%6,%7}, {%8,%9}, {%0,%1,%2,%3};"
        : "+f"(d[0]), "+f"(d[1]), "+f"(d[2]), "+f"(d[3])
        : "r"(a[0]), "r"(a[1]), "r"(a[2]), "r"(a[3]), "r"(b0), "r"(b1));
}

__device__ __forceinline__ uint32_t sw_off(int row, int c4) {
    return (uint32_t)row * 128u
         + ((((uint32_t)c4 >> 1) ^ ((uint32_t)row & 7u)) << 4)
         + ((uint32_t)c4 & 1u) * 8u;
}
__device__ __forceinline__ void store_hi16(unsigned char* base, int row, int c4, float4 v) {
    __half2 h01 = __floats2half2_rn(v.x, v.y);
    __half2 h23 = __floats2half2_rn(v.z, v.w);
    uint2 u;
    u.x = *reinterpret_cast<uint32_t*>(&h01);
    u.y = *reinterpret_cast<uint32_t*>(&h23);
    *(uint2*)(base + sw_off(row, c4)) = u;
}
__device__ __forceinline__ uint2 cvt16(float4 v) {
    __half2 h01 = __floats2half2_rn(v.x, v.y);
    __half2 h23 = __floats2half2_rn(v.z, v.w);
    return make_uint2(*reinterpret_cast<uint32_t*>(&h01), *reinterpret_cast<uint32_t*>(&h23));
}
__device__ __forceinline__ void split_store16(unsigned char* hi_base, unsigned char* lo_base,
                                              int row, int c4, float4 v) {
    __half2 h01 = __floats2half2_rn(v.x, v.y);
    __half2 h23 = __floats2half2_rn(v.z, v.w);
    float2 b01 = __half22float2(h01);
    float2 b23 = __half22float2(h23);
    __half2 l01 = __floats2half2_rn(v.x - b01.x, v.y - b01.y);
    __half2 l23 = __floats2half2_rn(v.z - b23.x, v.w - b23.y);
    uint32_t byte = sw_off(row, c4);
    uint2 uh, ul;
    uh.x = *reinterpret_cast<uint32_t*>(&h01);
    uh.y = *reinterpret_cast<uint32_t*>(&h23);
    ul.x = *reinterpret_cast<uint32_t*>(&l01);
    ul.y = *reinterpret_cast<uint32_t*>(&l23);
    *(uint2*)(hi_base + byte) = uh;
    *(uint2*)(lo_base + byte) = ul;
}
__device__ __forceinline__ void store_pair16(unsigned char* hi_base, unsigned char* lo_base,
                                             int row, int c, float v0, float v1) {
    __half2 h = __floats2half2_rn(v0, v1);
    float2 hf = __half22float2(h);
    __half2 l = __floats2half2_rn(v0 - hf.x, v1 - hf.y);
    uint32_t byte = (uint32_t)row * 128u
                  + ((((uint32_t)c >> 3) ^ ((uint32_t)row & 7u)) << 4)
                  + ((uint32_t)c & 7u) * 2u;
    *(uint32_t*)(hi_base + byte) = *reinterpret_cast<uint32_t*>(&h);
    *(uint32_t*)(lo_base + byte) = *reinterpret_cast<uint32_t*>(&l);
}

// 2-term fp16 mma (rho only).
__device__ __forceinline__ void mma_tile2(float acc[8][4], uint32_t sbase,
                                          uint32_t off_xhi, uint32_t off_xlo, uint32_t off_w,
                                          int w16, int sub, int l7) {
#pragma unroll
    for (int i = 0; i < 8; i++) { acc[i][0] = acc[i][1] = acc[i][2] = acc[i][3] = 0.f; }
#pragma unroll
    for (int kc = 0; kc < 4; kc++) {
        uint32_t ah[4], al[4];
        {
            int r = w16 + l7 + ((sub & 1) << 3);
            uint32_t cb = (uint32_t)kc * 32u + ((uint32_t)(sub >> 1) << 4);
            uint32_t off = (uint32_t)r * 128u + ((((cb >> 4) ^ (uint32_t)(r & 7))) << 4);
            ldsm_x4(ah, sbase + off_xhi + off);
            ldsm_x4(al, sbase + off_xlo + off);
        }
        const int kk = kc * 16 + l7 + ((sub & 1) << 3);
#pragma unroll
        for (int np = 0; np < 4; np++) {
            uint32_t bh[4];
            int ntc = 2 * np + (sub >> 1);
            uint32_t offB = (uint32_t)kk * 128u + ((uint32_t)(ntc ^ (kk & 7)) << 4);
            ldsm_x4_trans(bh, sbase + off_w + offB);
            mma_f16(acc[2 * np],     ah, bh[0], bh[1]);
            mma_f16(acc[2 * np],     al, bh[0], bh[1]);
            mma_f16(acc[2 * np + 1], ah, bh[2], bh[3]);
            mma_f16(acc[2 * np + 1], al, bh[2], bh[3]);
        }
    }
}

// ============================================================================
// phi (persistent, r12 structure): 1-term fp16 mma with B(W) fragments hoisted
// into registers (loop-invariant); h buffered as fp16; warp-local seg reduce.
// ============================================================================
__global__ void __launch_bounds__(256, 2) phi_kernel(
    const float* __restrict__ x, const float* __restrict__ w1,
    const float* __restrict__ b1, const int* __restrict__ seg, int nb)
{
    extern __shared__ unsigned char smem[];
    const uint32_t sbase = smem_u32(smem);
    const int t = threadIdx.x;
    const int lane = t & 31, wp = t >> 5;
    const int ntiles = (nb + 127) >> 7;
    int* sSeg = (int*)(smem + OFF_SEG);

    // stage W + bias, then hoist B fragments into registers (once)
    for (int i = t; i < 1024; i += 256)
        store_hi16(smem + OFF_WHI, i >> 4, i & 15, ((const float4*)w1)[i]);
    if (t < 64) ((float*)(smem + OFF_BIAS))[t] = b1[t];
    __syncthreads();

    const int w16 = wp * 16;
    const int sub = lane >> 3, l7 = lane & 7;

    uint32_t bfr[16][4];
#pragma unroll
    for (int kc = 0; kc < 4; kc++) {
        const int kk = kc * 16 + l7 + ((sub & 1) << 3);
#pragma unroll
        for (int np = 0; np < 4; np++) {
            int ntc = 2 * np + (sub >> 1);
            uint32_t offB = (uint32_t)kk * 128u + ((uint32_t)(ntc ^ (kk & 7)) << 4);
            ldsm_x4_trans(bfr[kc * 4 + np], sbase + OFF_WHI + offB);
        }
    }

    // prefetch first tile (converted to fp16 in regs)
    uint2 xp16[8];
    int sp;
    {
        long long n0 = (long long)blockIdx.x * 128;
        int nbl = (int)min(128LL, (long long)nb - n0);
        const float4* xg = (const float4*)(x + n0 * 64);
        const float4 z = make_float4(0.f, 0.f, 0.f, 0.f);
#pragma unroll
        for (int it = 0; it < 8; it++) {
            int i = t + 256 * it;
            xp16[it] = cvt16(((i >> 4) < nbl) ? xg[i] : z);
        }
        sp = (t < 128 && t < nbl) ? seg[n0 + t] : -1;
    }

    for (int tile = blockIdx.x; tile < ntiles; tile += gridDim.x) {
        // stage current tile
#pragma unroll
        for (int it = 0; it < 8; it++) {
            int i = t + 256 * it;
            *(uint2*)(smem + OFF_XHI + sw_off(i >> 4, i & 15)) = xp16[it];
        }
        if (t < 128) sSeg[t] = sp;
        if (t == 0)  sSeg[128] = -1;
        __syncthreads();               // sync1: tile + seg visible

        // mma: A from smem, B from registers
        float acc[8][4];
#pragma unroll
        for (int i = 0; i < 8; i++) { acc[i][0] = acc[i][1] = acc[i][2] = acc[i][3] = 0.f; }
#pragma unroll
        for (int kc = 0; kc < 4; kc++) {
            uint32_t ah[4];
            int r = w16 + l7 + ((sub & 1) << 3);
            uint32_t cb = (uint32_t)kc * 32u + ((uint32_t)(sub >> 1) << 4);
            uint32_t off = (uint32_t)r * 128u + ((((cb >> 4) ^ (uint32_t)(r & 7))) << 4);
            ldsm_x4(ah, sbase + OFF_XHI + off);
#pragma unroll
            for (int np = 0; np < 4; np++) {
                mma_f16(acc[2 * np],     ah, bfr[kc * 4 + np][0], bfr[kc * 4 + np][1]);
                mma_f16(acc[2 * np + 1], ah, bfr[kc * 4 + np][2], bfr[kc * 4 + np][3]);
            }
        }

        // epilogue: bias + relu -> fp16 h (136B row stride, conflict-free)
        {
            unsigned char* sHb = smem + OFF_H;
            const float* sB = (const float*)(smem + OFF_BIAS);
            int r0 = w16 + (lane >> 2);
            int c0 = (lane & 3) * 2;
#pragma unroll
            for (int nt = 0; nt < 8; nt++) {
                int c = nt * 8 + c0;
                float bx = sB[c], by = sB[c + 1];
                __half2 pa = __floats2half2_rn(fmaxf(acc[nt][0] + bx, 0.f),
                                               fmaxf(acc[nt][1] + by, 0.f));
                __half2 pb = __floats2half2_rn(fmaxf(acc[nt][2] + bx, 0.f),
                                               fmaxf(acc[nt][3] + by, 0.f));
                *(uint32_t*)(sHb + (uint32_t)r0 * 136u + 2u * c) =
                    *reinterpret_cast<uint32_t*>(&pa);
                *(uint32_t*)(sHb + (uint32_t)(r0 + 8) * 136u + 2u * c) =
                    *reinterpret_cast<uint32_t*>(&pb);
            }
        }

        // prefetch next tile (overlaps reduction)
        {
            int next = tile + gridDim.x;
            if (next < ntiles) {
                long long m0 = (long long)next * 128;
                int nbl = (int)min(128LL, (long long)nb - m0);
                const float4* xg = (const float4*)(x + m0 * 64);
                const float4 z = make_float4(0.f, 0.f, 0.f, 0.f);
#pragma unroll
                for (int it = 0; it < 8; it++) {
                    int i = t + 256 * it;
                    xp16[it] = cvt16(((i >> 4) < nbl) ? xg[i] : z);
                }
                sp = (t < 128 && t < nbl) ? seg[m0 + t] : -1;
            }
        }
        __syncwarp();   // own-warp h rows visible

        // warp-local segmented reduction: lane owns cols (2*lane, 2*lane+1)
        {
            uint32_t bmask;
            {
                bool b = false;
                if (lane < 16) b = sSeg[w16 + lane] != sSeg[w16 + lane + 1];
                bmask = __ballot_sync(0xffffffffu, b);
            }
            const unsigned char* sHb = smem + OFF_H;
            uint32_t v[16];
#pragma unroll
            for (int i = 0; i < 16; i++)
                v[i] = *(const uint32_t*)(sHb + (uint32_t)(w16 + i) * 136u + 4u * lane);
            float a0 = 0.f, a1 = 0.f;
#pragma unroll
            for (int i = 0; i < 16; i++) {
                float2 f = __half22float2(*reinterpret_cast<__half2*>(&v[i]));
                a0 += f.x; a1 += f.y;
                if (i == 15 || ((bmask >> i) & 1)) {
                    int s = sSeg[w16 + i];
                    if (s >= 0) {
                        atomicAdd(&g_sum[s * DIM + 2 * lane],     a0);
                        atomicAdd(&g_sum[s * DIM + 2 * lane + 1], a1);
                    }
                    a0 = 0.f; a1 = 0.f;
                }
            }
            if (lane == 0) {
                float c = 0.f;
#pragma unroll
                for (int i = 0; i < 16; i++) {
                    c += 1.f;
                    if (i == 15 || ((bmask >> i) & 1)) {
                        int s = sSeg[w16 + i];
                        if (s >= 0) atomicAdd(&g_cnt[s], c);
                        c = 0.f;
                    }
                }
            }
        }
        __syncthreads();   // sync2: seg/X consumed before next tile's stores
    }
}

// ============================================================================
// rho (persistent multi-tile, 2-term X split — unchanged from round 12).
// ============================================================================
__global__ void __launch_bounds__(256, 2) rho_kernel(
    const float* __restrict__ w2, const float* __restrict__ b2,
    const float* __restrict__ rw1, const float* __restrict__ rb1,
    const float* __restrict__ rw2, const float* __restrict__ rb2,
    float* __restrict__ out, int na)
{
    extern __shared__ unsigned char smem[];
    const uint32_t sbase = smem_u32(smem);
    const int t = threadIdx.x;
    const int lane = t & 31, wp = t >> 5;
    const int ntiles = (na + 127) >> 7;

    for (int i = t; i < 1024; i += 256) {
        store_hi16(smem + R_W2,  i >> 4, i & 15, ((const float4*)w2)[i]);
        store_hi16(smem + R_RW1, i >> 4, i & 15, ((const float4*)rw1)[i]);
    }
    if (t < 64)  { ((float*)(smem + R_B2))[t] = b2[t]; ((float*)(smem + R_RB1))[t] = rb1[t]; }
    if (t < 128) ((float*)(smem + R_RW2))[t] = rw2[t];

    const int w16 = wp * 16;
    const int sub = lane >> 3, l7 = lane & 7;
    const int r0 = w16 + (lane >> 2);
    const int c0 = (lane & 3) * 2;

    for (int tile = blockIdx.x; tile < ntiles; tile += gridDim.x) {
        const int a0 = tile * 128;
        const int na_local = min(128, na - a0);

        __syncthreads();
        if (t < 128) ((float*)(smem + R_CNT))[t] = (t < na_local) ? g_cnt[a0 + t] : 0.f;
        {
            const float4* xg = (const float4*)(g_sum + (long long)a0 * 64);
            const float4 z = make_float4(0.f, 0.f, 0.f, 0.f);
            for (int i = t; i < 128 * 16; i += 256) {
                float4 v = ((i >> 4) < na_local) ? xg[i] : z;
                split_store16(smem + R_XHI, smem + R_XLO, i >> 4, i & 15, v);
            }
        }
        __syncthreads();

        float acc[8][4];

        mma_tile2(acc, sbase, R_XHI, R_XLO, R_W2, w16, sub, l7);
        __syncwarp();
        {
            const float* sB2 = (const float*)(smem + R_B2);
            const float* sCnt = (const float*)(smem + R_CNT);
            float cA = sCnt[r0], cB = sCnt[r0 + 8];
#pragma unroll
            for (int nt = 0; nt < 8; nt++) {
                int c = nt * 8 + c0;
                float bx = sB2[c], by = sB2[c + 1];
                store_pair16(smem + R_XHI, smem + R_XLO, r0, c,
                             acc[nt][0] + cA * bx, acc[nt][1] + cA * by);
                store_pair16(smem + R_XHI, smem + R_XLO, r0 + 8, c,
                             acc[nt][2] + cB * bx, acc[nt][3] + cB * by);
            }
        }
        __syncwarp();

        mma_tile2(acc, sbase, R_XHI, R_XLO, R_RW1, w16, sub, l7);
        {
            const float* sRB1 = (const float*)(smem + R_RB1);
            const float* sRW2 = (const float*)(smem + R_RW2);
            float o0a = 0.f, o1a = 0.f, o0b = 0.f, o1b = 0.f;
#pragma unroll
            for (int nt = 0; nt < 8; nt++) {
                int c = nt * 8 + c0;
                float b0 = sRB1[c], b1v = sRB1[c + 1];
                float w00 = sRW2[2 * c],     w01 = sRW2[2 * c + 1];
                float w10 = sRW2[2 * c + 2], w11 = sRW2[2 * c + 3];
                float r00 = fmaxf(acc[nt][0] + b0,  0.f);
                float r01 = fmaxf(acc[nt][1] + b1v, 0.f);
                float r10 = fmaxf(acc[nt][2] + b0,  0.f);
                float r11 = fmaxf(acc[nt][3] + b1v, 0.f);
                o0a += r00 * w00 + r01 * w10;
                o1a += r00 * w01 + r01 * w11;
                o0b += r10 * w00 + r11 * w10;
                o1b += r10 * w01 + r11 * w11;
            }
#pragma unroll
            for (int m = 1; m <= 2; m <<= 1) {
                o0a += __shfl_xor_sync(0xffffffffu, o0a, m);
                o1a += __shfl_xor_sync(0xffffffffu, o1a, m);
                o0b += __shfl_xor_sync(0xffffffffu, o0b, m);
                o1b += __shfl_xor_sync(0xffffffffu, o1b, m);
            }
            if ((lane & 3) == 0) {
                float c0b = rb2[0], c1b = rb2[1];
                if (r0 < na_local)
                    *(float2*)(out + (size_t)(a0 + r0) * 2) = make_float2(o0a + c0b, o1a + c1b);
                if (r0 + 8 < na_local)
                    *(float2*)(out + (size_t)(a0 + r0 + 8) * 2) = make_float2(o0b + c0b, o1b + c1b);
            }
        }
    }
}

extern "C" void kernel_launch(void* const* d_in, const int* in_sizes, int n_in,
                              void* d_out, int out_size) {
    const float* neighbors = (const float*)d_in[0];
    const float* phi_w1 = (const float*)d_in[1];
    const float* phi_b1 = (const float*)d_in[2];
    const float* phi_w2 = (const float*)d_in[3];
    const float* phi_b2 = (const float*)d_in[4];
    const float* rho_w1 = (const float*)d_in[5];
    const float* rho_b1 = (const float*)d_in[6];
    const float* rho_w2 = (const float*)d_in[7];
    const float* rho_b2 = (const float*)d_in[8];
    const int*   seg    = (const int*)d_in[9];
    float* out = (float*)d_out;

    const int nb = in_sizes[0] / DIM;
    const int na = out_size / 2;

    void* p_sum = nullptr;
    void* p_cnt = nullptr;
    cudaGetSymbolAddress(&p_sum, g_sum);
    cudaGetSymbolAddress(&p_cnt, g_cnt);
    cudaMemsetAsync(p_sum, 0, (size_t)na * DIM * sizeof(float));
    cudaMemsetAsync(p_cnt, 0, (size_t)na * sizeof(float));

    cudaFuncSetAttribute(phi_kernel, cudaFuncAttributeMaxDynamicSharedMemorySize, PHI_SMEM);
    cudaFuncSetAttribute(rho_kernel, cudaFuncAttributeMaxDynamicSharedMemorySize, RHO_SMEM);

    const int ntiles = (nb + 127) / 128;
    int grid = 2 * 148;
    if (grid > ntiles) grid = ntiles;

    const int ntiles_rho = (na + 127) / 128;
    int grid_rho = (ntiles_rho + 1) / 2;
    if (grid_rho < 1) grid_rho = 1;

    phi_kernel<<<grid, 256, PHI_SMEM>>>(neighbors, phi_w1, phi_b1, seg, nb);
    rho_kernel<<<grid_rho, 256, RHO_SMEM>>>(phi_w2, phi_b2, rho_w1, rho_b1,
                                            rho_w2, rho_b2, out, na);
}

// round 16
// speedup vs baseline: 1.1232x; 1.1232x over previous
#include <cuda_runtime.h>
#include <cuda_fp16.h>
#include <cstdint>

#define DIM 64
#define N_AGENTS_MAX 50000

__device__ float g_sum[N_AGENTS_MAX * DIM];
__device__ float g_cnt[N_AGENTS_MAX];

// ---------------- phi smem layout (bytes) ----------------
#define OFF_WHI   0          // 8192   W1 fp16 [64][64] swizzled
#define OFF_XHI   8192       // 16384  X fp16 [128][64] swizzled
#define OFF_H     24576      // 17408  h fp16, 128 rows x 136B stride
#define OFF_BIAS  41984      // 256
#define OFF_SEG   42240      // 544
#define PHI_SMEM  42784

// ---------------- rho smem layout (bytes) ----------------
#define R_W2      0
#define R_RW1     8192
#define R_XHI     16384
#define R_XLO     32768
#define R_B2      49152
#define R_RB1     49408
#define R_RW2     49664
#define R_CNT     50176
#define RHO_SMEM  50688

__device__ __forceinline__ uint32_t smem_u32(const void* p) {
    uint32_t a;
    asm("{ .reg .u64 t; cvta.to.shared.u64 t, %1; cvt.u32.u64 %0, t; }" : "=r"(a) : "l"(p));
    return a;
}
__device__ __forceinline__ void ldsm_x4(uint32_t* r, uint32_t addr) {
    asm volatile("ldmatrix.sync.aligned.m8n8.x4.shared.b16 {%0,%1,%2,%3}, [%4];"
        : "=r"(r[0]), "=r"(r[1]), "=r"(r[2]), "=r"(r[3]) : "r"(addr));
}
__device__ __forceinline__ void ldsm_x4_trans(uint32_t* r, uint32_t addr) {
    asm volatile("ldmatrix.sync.aligned.m8n8.x4.trans.shared.b16 {%0,%1,%2,%3}, [%4];"
        : "=r"(r[0]), "=r"(r[1]), "=r"(r[2]), "=r"(r[3]) : "r"(addr));
}
__device__ __forceinline__ void mma_f16(float* d, const uint32_t* a, uint32_t b0, uint32_t b1) {
    asm volatile("mma.sync.aligned.m16n8k16.row.col.f32.f16.f16.f32 "
        "{%0,%1,%2,%3}, {%4,%5,%6,%7}, {%8,%9}, {%0,%1,%2,%3};"
        : "+f"(d[0]), "+f"(d[1]), "+f"(d[2]), "+f"(d[3])
        : "r"(a[0]), "r"(a[1]), "r"(a[2]), "r"(a[3]), "r"(b0), "r"(b1));
}

__device__ __forceinline__ uint32_t sw_off(int row, int c4) {
    return (uint32_t)row * 128u
         + ((((uint32_t)c4 >> 1) ^ ((uint32_t)row & 7u)) << 4)
         + ((uint32_t)c4 & 1u) * 8u;
}
__device__ __forceinline__ void store_hi16(unsigned char* base, int row, int c4, float4 v) {
    __half2 h01 = __floats2half2_rn(v.x, v.y);
    __half2 h23 = __floats2half2_rn(v.z, v.w);
    uint2 u;
    u.x = *reinterpret_cast<uint32_t*>(&h01);
    u.y = *reinterpret_cast<uint32_t*>(&h23);
    *(uint2*)(base + sw_off(row, c4)) = u;
}
__device__ __forceinline__ void split_store16(unsigned char* hi_base, unsigned char* lo_base,
                                              int row, int c4, float4 v) {
    __half2 h01 = __floats2half2_rn(v.x, v.y);
    __half2 h23 = __floats2half2_rn(v.z, v.w);
    float2 b01 = __half22float2(h01);
    float2 b23 = __half22float2(h23);
    __half2 l01 = __floats2half2_rn(v.x - b01.x, v.y - b01.y);
    __half2 l23 = __floats2half2_rn(v.z - b23.x, v.w - b23.y);
    uint32_t byte = sw_off(row, c4);
    uint2 uh, ul;
    uh.x = *reinterpret_cast<uint32_t*>(&h01);
    uh.y = *reinterpret_cast<uint32_t*>(&h23);
    ul.x = *reinterpret_cast<uint32_t*>(&l01);
    ul.y = *reinterpret_cast<uint32_t*>(&l23);
    *(uint2*)(hi_base + byte) = uh;
    *(uint2*)(lo_base + byte) = ul;
}
__device__ __forceinline__ void store_pair16(unsigned char* hi_base, unsigned char* lo_base,
                                             int row, int c, float v0, float v1) {
    __half2 h = __floats2half2_rn(v0, v1);
    float2 hf = __half22float2(h);
    __half2 l = __floats2half2_rn(v0 - hf.x, v1 - hf.y);
    uint32_t byte = (uint32_t)row * 128u
                  + ((((uint32_t)c >> 3) ^ ((uint32_t)row & 7u)) << 4)
                  + ((uint32_t)c & 7u) * 2u;
    *(uint32_t*)(hi_base + byte) = *reinterpret_cast<uint32_t*>(&h);
    *(uint32_t*)(lo_base + byte) = *reinterpret_cast<uint32_t*>(&l);
}

// 1-term fp16 mma over one 128x64 tile (phi).
__device__ __forceinline__ void mma_tile1(float acc[8][4], uint32_t sbase,
                                          uint32_t off_x, uint32_t off_w,
                                          int w16, int sub, int l7) {
#pragma unroll
    for (int i = 0; i < 8; i++) { acc[i][0] = acc[i][1] = acc[i][2] = acc[i][3] = 0.f; }
#pragma unroll
    for (int kc = 0; kc < 4; kc++) {
        uint32_t ah[4];
        {
            int r = w16 + l7 + ((sub & 1) << 3);
            uint32_t cb = (uint32_t)kc * 32u + ((uint32_t)(sub >> 1) << 4);
            uint32_t off = (uint32_t)r * 128u + ((((cb >> 4) ^ (uint32_t)(r & 7))) << 4);
            ldsm_x4(ah, sbase + off_x + off);
        }
        const int kk = kc * 16 + l7 + ((sub & 1) << 3);
#pragma unroll
        for (int np = 0; np < 4; np++) {
            uint32_t bh[4];
            int ntc = 2 * np + (sub >> 1);
            uint32_t offB = (uint32_t)kk * 128u + ((uint32_t)(ntc ^ (kk & 7)) << 4);
            ldsm_x4_trans(bh, sbase + off_w + offB);
            mma_f16(acc[2 * np],     ah, bh[0], bh[1]);
            mma_f16(acc[2 * np + 1], ah, bh[2], bh[3]);
        }
    }
}

// 2-term fp16 mma (rho).
__device__ __forceinline__ void mma_tile2(float acc[8][4], uint32_t sbase,
                                          uint32_t off_xhi, uint32_t off_xlo, uint32_t off_w,
                                          int w16, int sub, int l7) {
#pragma unroll
    for (int i = 0; i < 8; i++) { acc[i][0] = acc[i][1] = acc[i][2] = acc[i][3] = 0.f; }
#pragma unroll
    for (int kc = 0; kc < 4; kc++) {
        uint32_t ah[4], al[4];
        {
            int r = w16 + l7 + ((sub & 1) << 3);
            uint32_t cb = (uint32_t)kc * 32u + ((uint32_t)(sub >> 1) << 4);
            uint32_t off = (uint32_t)r * 128u + ((((cb >> 4) ^ (uint32_t)(r & 7))) << 4);
            ldsm_x4(ah, sbase + off_xhi + off);
            ldsm_x4(al, sbase + off_xlo + off);
        }
        const int kk = kc * 16 + l7 + ((sub & 1) << 3);
#pragma unroll
        for (int np = 0; np < 4; np++) {
            uint32_t bh[4];
            int ntc = 2 * np + (sub >> 1);
            uint32_t offB = (uint32_t)kk * 128u + ((uint32_t)(ntc ^ (kk & 7)) << 4);
            ldsm_x4_trans(bh, sbase + off_w + offB);
            mma_f16(acc[2 * np],     ah, bh[0], bh[1]);
            mma_f16(acc[2 * np],     al, bh[0], bh[1]);
            mma_f16(acc[2 * np + 1], ah, bh[2], bh[3]);
            mma_f16(acc[2 * np + 1], al, bh[2], bh[3]);
        }
    }
}

// ============================================================================
// phi: r12 structure exactly, with ONE change — h buffered as fp16 (halves
// the instruction count of the epilogue-store and reduction-load phases).
// ============================================================================
__global__ void __launch_bounds__(256, 2) phi_kernel(
    const float* __restrict__ x, const float* __restrict__ w1,
    const float* __restrict__ b1, const int* __restrict__ seg, int nb)
{
    extern __shared__ unsigned char smem[];
    const uint32_t sbase = smem_u32(smem);
    const int t = threadIdx.x;
    const int lane = t & 31, wp = t >> 5;
    const int ntiles = (nb + 127) >> 7;
    int* sSeg = (int*)(smem + OFF_SEG);

    for (int i = t; i < 1024; i += 256)
        store_hi16(smem + OFF_WHI, i >> 4, i & 15, ((const float4*)w1)[i]);
    if (t < 64) ((float*)(smem + OFF_BIAS))[t] = b1[t];

    // prefetch first tile (float4 regs, r12-style)
    float4 xp[8];
    int sp;
    {
        long long n0 = (long long)blockIdx.x * 128;
        int nbl = (int)min(128LL, (long long)nb - n0);
        const float4* xg = (const float4*)(x + n0 * 64);
        const float4 z = make_float4(0.f, 0.f, 0.f, 0.f);
#pragma unroll
        for (int it = 0; it < 8; it++) {
            int i = t + 256 * it;
            xp[it] = ((i >> 4) < nbl) ? xg[i] : z;
        }
        sp = (t < 128 && t < nbl) ? seg[n0 + t] : -1;
    }

    const int w16 = wp * 16;
    const int sub = lane >> 3, l7 = lane & 7;

    for (int tile = blockIdx.x; tile < ntiles; tile += gridDim.x) {
#pragma unroll
        for (int it = 0; it < 8; it++) {
            int i = t + 256 * it;
            store_hi16(smem + OFF_XHI, i >> 4, i & 15, xp[it]);
        }
        if (t < 128) sSeg[t] = sp;
        if (t == 0)  sSeg[128] = -1;
        __syncthreads();               // sync1: tile + seg visible

        float acc[8][4];
        mma_tile1(acc, sbase, OFF_XHI, OFF_WHI, w16, sub, l7);

        // epilogue: bias + relu -> fp16 h (136B row stride, conflict-free)
        {
            unsigned char* sHb = smem + OFF_H;
            const float* sB = (const float*)(smem + OFF_BIAS);
            int r0 = w16 + (lane >> 2);
            int c0 = (lane & 3) * 2;
#pragma unroll
            for (int nt = 0; nt < 8; nt++) {
                int c = nt * 8 + c0;
                float bx = sB[c], by = sB[c + 1];
                __half2 pa = __floats2half2_rn(fmaxf(acc[nt][0] + bx, 0.f),
                                               fmaxf(acc[nt][1] + by, 0.f));
                __half2 pb = __floats2half2_rn(fmaxf(acc[nt][2] + bx, 0.f),
                                               fmaxf(acc[nt][3] + by, 0.f));
                *(uint32_t*)(sHb + (uint32_t)r0 * 136u + 2u * c) =
                    *reinterpret_cast<uint32_t*>(&pa);
                *(uint32_t*)(sHb + (uint32_t)(r0 + 8) * 136u + 2u * c) =
                    *reinterpret_cast<uint32_t*>(&pb);
            }
        }

        // prefetch next tile (overlaps reduction)
        {
            int next = tile + gridDim.x;
            if (next < ntiles) {
                long long m0 = (long long)next * 128;
                int nbl = (int)min(128LL, (long long)nb - m0);
                const float4* xg = (const float4*)(x + m0 * 64);
                const float4 z = make_float4(0.f, 0.f, 0.f, 0.f);
#pragma unroll
                for (int it = 0; it < 8; it++) {
                    int i = t + 256 * it;
                    xp[it] = ((i >> 4) < nbl) ? xg[i] : z;
                }
                sp = (t < 128 && t < nbl) ? seg[m0 + t] : -1;
            }
        }
        __syncwarp();   // own-warp h rows visible

        // warp-local segmented reduction: lane owns cols (2*lane, 2*lane+1)
        {
            uint32_t bmask;
            {
                bool b = false;
                if (lane < 16) b = sSeg[w16 + lane] != sSeg[w16 + lane + 1];
                bmask = __ballot_sync(0xffffffffu, b);
            }
            const unsigned char* sHb = smem + OFF_H;
            uint32_t v[16];
#pragma unroll
            for (int i = 0; i < 16; i++)
                v[i] = *(const uint32_t*)(sHb + (uint32_t)(w16 + i) * 136u + 4u * lane);
            float a0 = 0.f, a1 = 0.f;
#pragma unroll
            for (int i = 0; i < 16; i++) {
                float2 f = __half22float2(*reinterpret_cast<__half2*>(&v[i]));
                a0 += f.x; a1 += f.y;
                if (i == 15 || ((bmask >> i) & 1)) {
                    int s = sSeg[w16 + i];
                    if (s >= 0) {
                        atomicAdd(&g_sum[s * DIM + 2 * lane],     a0);
                        atomicAdd(&g_sum[s * DIM + 2 * lane + 1], a1);
                    }
                    a0 = 0.f; a1 = 0.f;
                }
            }
            if (lane == 0) {
                float c = 0.f;
#pragma unroll
                for (int i = 0; i < 16; i++) {
                    c += 1.f;
                    if (i == 15 || ((bmask >> i) & 1)) {
                        int s = sSeg[w16 + i];
                        if (s >= 0) atomicAdd(&g_cnt[s], c);
                        c = 0.f;
                    }
                }
            }
        }
        __syncthreads();   // sync2: seg/X consumed before next tile's stores
    }
}

// ============================================================================
// rho (r12 code; grid now ntiles/4 for better weight-staging amortization).
// ============================================================================
__global__ void __launch_bounds__(256, 2) rho_kernel(
    const float* __restrict__ w2, const float* __restrict__ b2,
    const float* __restrict__ rw1, const float* __restrict__ rb1,
    const float* __restrict__ rw2, const float* __restrict__ rb2,
    float* __restrict__ out, int na)
{
    extern __shared__ unsigned char smem[];
    const uint32_t sbase = smem_u32(smem);
    const int t = threadIdx.x;
    const int lane = t & 31, wp = t >> 5;
    const int ntiles = (na + 127) >> 7;

    for (int i = t; i < 1024; i += 256) {
        store_hi16(smem + R_W2,  i >> 4, i & 15, ((const float4*)w2)[i]);
        store_hi16(smem + R_RW1, i >> 4, i & 15, ((const float4*)rw1)[i]);
    }
    if (t < 64)  { ((float*)(smem + R_B2))[t] = b2[t]; ((float*)(smem + R_RB1))[t] = rb1[t]; }
    if (t < 128) ((float*)(smem + R_RW2))[t] = rw2[t];

    const int w16 = wp * 16;
    const int sub = lane >> 3, l7 = lane & 7;
    const int r0 = w16 + (lane >> 2);
    const int c0 = (lane & 3) * 2;

    for (int tile = blockIdx.x; tile < ntiles; tile += gridDim.x) {
        const int a0 = tile * 128;
        const int na_local = min(128, na - a0);

        __syncthreads();
        if (t < 128) ((float*)(smem + R_CNT))[t] = (t < na_local) ? g_cnt[a0 + t] : 0.f;
        {
            const float4* xg = (const float4*)(g_sum + (long long)a0 * 64);
            const float4 z = make_float4(0.f, 0.f, 0.f, 0.f);
            for (int i = t; i < 128 * 16; i += 256) {
                float4 v = ((i >> 4) < na_local) ? xg[i] : z;
                split_store16(smem + R_XHI, smem + R_XLO, i >> 4, i & 15, v);
            }
        }
        __syncthreads();

        float acc[8][4];

        mma_tile2(acc, sbase, R_XHI, R_XLO, R_W2, w16, sub, l7);
        __syncwarp();
        {
            const float* sB2 = (const float*)(smem + R_B2);
            const float* sCnt = (const float*)(smem + R_CNT);
            float cA = sCnt[r0], cB = sCnt[r0 + 8];
#pragma unroll
            for (int nt = 0; nt < 8; nt++) {
                int c = nt * 8 + c0;
                float bx = sB2[c], by = sB2[c + 1];
                store_pair16(smem + R_XHI, smem + R_XLO, r0, c,
                             acc[nt][0] + cA * bx, acc[nt][1] + cA * by);
                store_pair16(smem + R_XHI, smem + R_XLO, r0 + 8, c,
                             acc[nt][2] + cB * bx, acc[nt][3] + cB * by);
            }
        }
        __syncwarp();

        mma_tile2(acc, sbase, R_XHI, R_XLO, R_RW1, w16, sub, l7);
        {
            const float* sRB1 = (const float*)(smem + R_RB1);
            const float* sRW2 = (const float*)(smem + R_RW2);
            float o0a = 0.f, o1a = 0.f, o0b = 0.f, o1b = 0.f;
#pragma unroll
            for (int nt = 0; nt < 8; nt++) {
                int c = nt * 8 + c0;
                float b0 = sRB1[c], b1v = sRB1[c + 1];
                float w00 = sRW2[2 * c],     w01 = sRW2[2 * c + 1];
                float w10 = sRW2[2 * c + 2], w11 = sRW2[2 * c + 3];
                float r00 = fmaxf(acc[nt][0] + b0,  0.f);
                float r01 = fmaxf(acc[nt][1] + b1v, 0.f);
                float r10 = fmaxf(acc[nt][2] + b0,  0.f);
                float r11 = fmaxf(acc[nt][3] + b1v, 0.f);
                o0a += r00 * w00 + r01 * w10;
                o1a += r00 * w01 + r01 * w11;
                o0b += r10 * w00 + r11 * w10;
                o1b += r10 * w01 + r11 * w11;
            }
#pragma unroll
            for (int m = 1; m <= 2; m <<= 1) {
                o0a += __shfl_xor_sync(0xffffffffu, o0a, m);
                o1a += __shfl_xor_sync(0xffffffffu, o1a, m);
                o0b += __shfl_xor_sync(0xffffffffu, o0b, m);
                o1b += __shfl_xor_sync(0xffffffffu, o1b, m);
            }
            if ((lane & 3) == 0) {
                float c0b = rb2[0], c1b = rb2[1];
                if (r0 < na_local)
                    *(float2*)(out + (size_t)(a0 + r0) * 2) = make_float2(o0a + c0b, o1a + c1b);
                if (r0 + 8 < na_local)
                    *(float2*)(out + (size_t)(a0 + r0 + 8) * 2) = make_float2(o0b + c0b, o1b + c1b);
            }
        }
    }
}

extern "C" void kernel_launch(void* const* d_in, const int* in_sizes, int n_in,
                              void* d_out, int out_size) {
    const float* neighbors = (const float*)d_in[0];
    const float* phi_w1 = (const float*)d_in[1];
    const float* phi_b1 = (const float*)d_in[2];
    const float* phi_w2 = (const float*)d_in[3];
    const float* phi_b2 = (const float*)d_in[4];
    const float* rho_w1 = (const float*)d_in[5];
    const float* rho_b1 = (const float*)d_in[6];
    const float* rho_w2 = (const float*)d_in[7];
    const float* rho_b2 = (const float*)d_in[8];
    const int*   seg    = (const int*)d_in[9];
    float* out = (float*)d_out;

    const int nb = in_sizes[0] / DIM;
    const int na = out_size / 2;

    void* p_sum = nullptr;
    void* p_cnt = nullptr;
    cudaGetSymbolAddress(&p_sum, g_sum);
    cudaGetSymbolAddress(&p_cnt, g_cnt);
    cudaMemsetAsync(p_sum, 0, (size_t)na * DIM * sizeof(float));
    cudaMemsetAsync(p_cnt, 0, (size_t)na * sizeof(float));

    cudaFuncSetAttribute(phi_kernel, cudaFuncAttributeMaxDynamicSharedMemorySize, PHI_SMEM);
    cudaFuncSetAttribute(rho_kernel, cudaFuncAttributeMaxDynamicSharedMemorySize, RHO_SMEM);

    const int ntiles = (nb + 127) / 128;
    int grid = 2 * 148;
    if (grid > ntiles) grid = ntiles;

    const int ntiles_rho = (na + 127) / 128;
    int grid_rho = (ntiles_rho + 3) / 4;
    if (grid_rho < 1) grid_rho = 1;

    phi_kernel<<<grid, 256, PHI_SMEM>>>(neighbors, phi_w1, phi_b1, seg, nb);
    rho_kernel<<<grid_rho, 256, RHO_SMEM>>>(phi_w2, phi_b2, rho_w1, rho_b1,
                                            rho_w2, rho_b2, out, na);
}